// round 12
// baseline (speedup 1.0000x reference)
#include <cuda_runtime.h>
#include <cuda_bf16.h>

// Problem constants (fixed shapes)
#define BATCH 4
#define CIN   64
#define HNUM  96
#define WNUM  96
#define G     8
#define OG    8
#define OGH   4            // channels handled per block
#define IG    8
#define KW    7
#define PAD   3
#define PLANE (HNUM * WNUM)

// Tiling: 192 threads = 12 rows x 16 thread-cols, 2 adjacent px per thread.
#define TH 12
#define TW 32
#define TCN 16
#define NTHREADS 192
#define HH  (TH + KW - 1)   // 18
#define HWD (TW + KW - 1)   // 38
#define KVSTR 76            // floats per row: 38 px * 2 (k,v). 304B, 16B-aligned.

// Polynomial exp2 on the FMA/ALU pipes (no MUFU). Rel err ~2e-7.
__device__ __forceinline__ float exp2_poly(float l) {
    float nf = floorf(l);
    float f  = l - nf;
    int   ni = (int)nf;
    float p = fmaf(f, 0.0096181291f, 0.0555036107f);
    p = fmaf(f, p, 0.2402264308f);
    p = fmaf(f, p, 0.6931471825f);
    p = fmaf(f, p, 1.0f);
    return __int_as_float(__float_as_int(p) + ni * 8388608); // + (ni<<23)
}

template <bool POLY>
__device__ __forceinline__ float expo(float l) {
    if (POLY) return exp2_poly(l);
    float e;
    asm("ex2.approx.f32 %0, %1;" : "=f"(e) : "f"(l));
    return e;
}

// One channel, one pixel pair. kvrow0: &kv[c][y_][2*x_]. embc: 7 emb values.
// ROWEMB: emb indexed by di; else by dj.
template <bool POLY, bool ROWEMB>
__device__ __forceinline__ float2 chan(const float* __restrict__ kvrow0,
                                       float qs0, float qs1,
                                       const float* __restrict__ embc)
{
    float qe0a[KW], qe1a[KW];
    if (!ROWEMB) {
        #pragma unroll
        for (int t = 0; t < KW; t++) {
            qe0a[t] = qs0 * embc[t];
            qe1a[t] = qs1 * embc[t];
        }
    }
    float ss0 = 0.f, ss1 = 0.f, ac0 = 0.f, ac1 = 0.f;
    #pragma unroll
    for (int di = 0; di < KW; di++) {
        const float4* rp = (const float4*)(kvrow0 + di * KVSTR);
        float4 a0 = rp[0], a1 = rp[1], a2 = rp[2], a3 = rp[3];
        float kk[8] = {a0.x, a0.z, a1.x, a1.z, a2.x, a2.z, a3.x, a3.z};
        float vv[8] = {a0.y, a0.w, a1.y, a1.w, a2.y, a2.w, a3.y, a3.w};
        float qe0 = 0.f, qe1 = 0.f;
        if (ROWEMB) { const float eh = embc[di]; qe0 = qs0 * eh; qe1 = qs1 * eh; }
        #pragma unroll
        for (int dj = 0; dj < KW; dj++) {
            const float b0 = ROWEMB ? qe0 : qe0a[dj];
            const float b1 = ROWEMB ? qe1 : qe1a[dj];
            float e0 = expo<POLY>(fmaf(qs0, kk[dj], b0));
            ss0 += e0; ac0 = fmaf(e0, vv[dj], ac0);
            float e1 = expo<POLY>(fmaf(qs1, kk[dj + 1], b1));
            ss1 += e1; ac1 = fmaf(e1, vv[dj + 1], ac1);
        }
    }
    return make_float2(__fdividef(ac0, ss0), __fdividef(ac1, ss1));
}

__global__ __launch_bounds__(NTHREADS)
void attn_fused_kernel(const float* __restrict__ x,
                       const float* __restrict__ wq,
                       const float* __restrict__ wk,
                       const float* __restrict__ wv,
                       const float* __restrict__ h_emb,
                       const float* __restrict__ w_emb,
                       float* __restrict__ out)
{
    // k,v interleaved per pixel for LDS.128: [ch][row][2*col + {k,v}]
    __shared__ __align__(16) float kv_s[OGH][HH][KVSTR];   // 21.4 KB
    __shared__ float  wq_s[OGH * IG];
    __shared__ float2 wkv_s[OGH * IG];
    __shared__ float  emb_s[OGH * KW];

    const int tid  = threadIdx.x;
    const int bz   = blockIdx.z;       // ((b*8+g)*2 + half)
    const int half_ = bz & 1;
    const int g    = (bz >> 1) & 7;
    const int b    = bz >> 4;
    const int h0   = blockIdx.y * TH;
    const int w0   = blockIdx.x * TW;

    if (tid < 32) {
        const int wi = g * 64 + half_ * 32 + tid;
        wq_s[tid]  = wq[wi];
        wkv_s[tid] = make_float2(wk[wi], wv[wi]);
    } else if (tid >= 32 && tid < 60) {
        const float* ep = half_ ? w_emb : h_emb;
        emb_s[tid - 32] = ep[g * 28 + (tid - 32)];
    }
    __syncthreads();

    const float* xg = x + (size_t)(b * CIN + g * IG) * PLANE;
    const int cbase = half_ * OGH;

    // --- phase 1: grouped 1x1 conv k,v over haloed tile -> interleaved SMEM ---
    for (int p = tid; p < HH * HWD; p += NTHREADS) {
        const int yy = p / HWD;
        const int xx = p - yy * HWD;
        const int gy = h0 + yy - PAD;
        const int gx = w0 + xx - PAD;
        const bool inb = ((unsigned)gy < HNUM) & ((unsigned)gx < WNUM);
        const float* xb = xg + gy * WNUM + gx;
        float xi[IG];
        #pragma unroll
        for (int i = 0; i < IG; i++)
            xi[i] = inb ? __ldg(xb + i * PLANE) : 0.0f;
        #pragma unroll
        for (int c = 0; c < OGH; c++) {
            float kc = 0.0f, vc = 0.0f;
            #pragma unroll
            for (int i = 0; i < IG; i++) {
                const float2 w2 = wkv_s[c * IG + i];
                kc = fmaf(w2.x, xi[i], kc);
                vc = fmaf(w2.y, xi[i], vc);
            }
            *(float2*)&kv_s[c][yy][2 * xx] = make_float2(kc, vc);
        }
    }
    __syncthreads();

    // --- phase 2: attention; each thread owns 2 adjacent pixels, 4 channels ---
    const int tc = tid & (TCN - 1);
    const int y_ = tid >> 4;
    const int x_ = 2 * tc;
    const int gh = h0 + y_;
    const int gw = w0 + x_;

    const float LOG2E = 1.4426950408889634f;

    float qsv[OGH][2];
    {
        float xi0[IG], xi1[IG];
        const float* xb = xg + gh * WNUM + gw;
        #pragma unroll
        for (int i = 0; i < IG; i++) {
            float2 t = __ldg((const float2*)(xb + i * PLANE));
            xi0[i] = t.x; xi1[i] = t.y;
        }
        #pragma unroll
        for (int c = 0; c < OGH; c++) {
            float q0 = 0.0f, q1 = 0.0f;
            #pragma unroll
            for (int i = 0; i < IG; i++) {
                q0 = fmaf(wq_s[c * IG + i], xi0[i], q0);
                q1 = fmaf(wq_s[c * IG + i], xi1[i], q1);
            }
            qsv[c][0] = q0 * LOG2E;
            qsv[c][1] = q1 * LOG2E;
        }
    }

    float* op = out + ((size_t)(b * CIN + g * OG + cbase) * HNUM + gh) * WNUM + gw;

    if (half_ == 0) {
        // channels 0..3: emb varies along patch ROW (di)
        // channel 0 -> polynomial exp (FMA pipe); 1..3 -> MUFU ex2.
        {
            float2 o = chan<true, true>(&kv_s[0][y_][2 * x_],
                                        qsv[0][0], qsv[0][1], &emb_s[0]);
            *(float2*)&op[0] = o;
        }
        #pragma unroll 1
        for (int c = 1; c < OGH; c++) {
            float2 o = chan<false, true>(&kv_s[c][y_][2 * x_],
                                         qsv[c][0], qsv[c][1], &emb_s[c * KW]);
            *(float2*)&op[(size_t)c * PLANE] = o;
        }
    } else {
        // channels 4..7: emb varies along patch COL (dj)
        {
            float2 o = chan<true, false>(&kv_s[0][y_][2 * x_],
                                         qsv[0][0], qsv[0][1], &emb_s[0]);
            *(float2*)&op[0] = o;
        }
        #pragma unroll 1
        for (int c = 1; c < OGH; c++) {
            float2 o = chan<false, false>(&kv_s[c][y_][2 * x_],
                                          qsv[c][0], qsv[c][1], &emb_s[c * KW]);
            *(float2*)&op[(size_t)c * PLANE] = o;
        }
    }
}

extern "C" void kernel_launch(void* const* d_in, const int* in_sizes, int n_in,
                              void* d_out, int out_size)
{
    const float* x     = (const float*)d_in[0];
    const float* wq    = (const float*)d_in[1];
    const float* wk    = (const float*)d_in[2];
    const float* wv    = (const float*)d_in[3];
    const float* h_emb = (const float*)d_in[4];
    const float* w_emb = (const float*)d_in[5];
    float* out = (float*)d_out;

    dim3 grid(WNUM / TW, HNUM / TH, BATCH * G * 2);  // (3, 8, 64) = 1536 blocks
    dim3 block(NTHREADS);
    attn_fused_kernel<<<grid, block>>>(x, wq, wk, wv, h_emb, w_emb, out);
}

// round 13
// speedup vs baseline: 1.1694x; 1.1694x over previous
#include <cuda_runtime.h>
#include <cuda_bf16.h>

// Problem constants (fixed shapes)
#define BATCH 4
#define CIN   64
#define HNUM  96
#define WNUM  96
#define G     8
#define OG    8
#define OGH   4            // channels handled per block
#define IG    8
#define KW    7
#define PAD   3
#define PLANE (HNUM * WNUM)

// Tiling: 192 threads = 12 rows x 16 thread-cols, 2 adjacent px per thread.
#define TH 12
#define TW 32
#define TCN 16
#define NTHREADS 192
#define HH  (TH + KW - 1)   // 18
#define HWD (TW + KW - 1)   // 38
#define KVSTR 76            // floats per row: 38 px * 2 (k,v). 304B, 16B-aligned.

__device__ __forceinline__ float ex2f(float l) {
    float e;
    asm("ex2.approx.f32 %0, %1;" : "=f"(e) : "f"(l));
    return e;
}

// Two channels processed concurrently -> 4 independent exp/accum chains.
// kvA/kvB: &kv[c][y_][2*x_] for the two channels. eA/eB: 7 emb values each.
template <bool ROWEMB>
__device__ __forceinline__ void chan2(const float* __restrict__ kvA,
                                      const float* __restrict__ kvB,
                                      float qA0, float qA1, float qB0, float qB1,
                                      const float* __restrict__ eA,
                                      const float* __restrict__ eB,
                                      float2& oA, float2& oB)
{
    float qeA0[KW], qeA1[KW], qeB0[KW], qeB1[KW];
    if (!ROWEMB) {
        #pragma unroll
        for (int t = 0; t < KW; t++) {
            qeA0[t] = qA0 * eA[t];  qeA1[t] = qA1 * eA[t];
            qeB0[t] = qB0 * eB[t];  qeB1[t] = qB1 * eB[t];
        }
    }
    float sA0 = 0.f, sA1 = 0.f, aA0 = 0.f, aA1 = 0.f;
    float sB0 = 0.f, sB1 = 0.f, aB0 = 0.f, aB1 = 0.f;

    #pragma unroll
    for (int di = 0; di < KW; di++) {
        const float4* rA = (const float4*)(kvA + di * KVSTR);
        const float4* rB = (const float4*)(kvB + di * KVSTR);
        float4 A0 = rA[0], A1 = rA[1], A2 = rA[2], A3 = rA[3];
        float4 B0 = rB[0], B1 = rB[1], B2 = rB[2], B3 = rB[3];
        float kA[8] = {A0.x, A0.z, A1.x, A1.z, A2.x, A2.z, A3.x, A3.z};
        float vA[8] = {A0.y, A0.w, A1.y, A1.w, A2.y, A2.w, A3.y, A3.w};
        float kB[8] = {B0.x, B0.z, B1.x, B1.z, B2.x, B2.z, B3.x, B3.z};
        float vB[8] = {B0.y, B0.w, B1.y, B1.w, B2.y, B2.w, B3.y, B3.w};

        float bA0 = 0.f, bA1 = 0.f, bB0 = 0.f, bB1 = 0.f;
        if (ROWEMB) {
            bA0 = qA0 * eA[di]; bA1 = qA1 * eA[di];
            bB0 = qB0 * eB[di]; bB1 = qB1 * eB[di];
        }
        #pragma unroll
        for (int dj = 0; dj < KW; dj++) {
            const float cA0 = ROWEMB ? bA0 : qeA0[dj];
            const float cA1 = ROWEMB ? bA1 : qeA1[dj];
            const float cB0 = ROWEMB ? bB0 : qeB0[dj];
            const float cB1 = ROWEMB ? bB1 : qeB1[dj];
            // 4 independent chains interleaved
            float e0 = ex2f(fmaf(qA0, kA[dj],     cA0));
            float e1 = ex2f(fmaf(qA1, kA[dj + 1], cA1));
            float e2 = ex2f(fmaf(qB0, kB[dj],     cB0));
            float e3 = ex2f(fmaf(qB1, kB[dj + 1], cB1));
            sA0 += e0; aA0 = fmaf(e0, vA[dj],     aA0);
            sA1 += e1; aA1 = fmaf(e1, vA[dj + 1], aA1);
            sB0 += e2; aB0 = fmaf(e2, vB[dj],     aB0);
            sB1 += e3; aB1 = fmaf(e3, vB[dj + 1], aB1);
        }
    }
    oA = make_float2(__fdividef(aA0, sA0), __fdividef(aA1, sA1));
    oB = make_float2(__fdividef(aB0, sB0), __fdividef(aB1, sB1));
}

__global__ __launch_bounds__(NTHREADS)
void attn_fused_kernel(const float* __restrict__ x,
                       const float* __restrict__ wq,
                       const float* __restrict__ wk,
                       const float* __restrict__ wv,
                       const float* __restrict__ h_emb,
                       const float* __restrict__ w_emb,
                       float* __restrict__ out)
{
    // k,v interleaved per pixel for LDS.128: [ch][row][2*col + {k,v}]
    __shared__ __align__(16) float kv_s[OGH][HH][KVSTR];   // 21.4 KB
    __shared__ float  wq_s[OGH * IG];
    __shared__ float2 wkv_s[OGH * IG];
    __shared__ float  emb_s[OGH * KW];

    const int tid  = threadIdx.x;
    const int bz   = blockIdx.z;       // ((b*8+g)*2 + half)
    const int half_ = bz & 1;
    const int g    = (bz >> 1) & 7;
    const int b    = bz >> 4;
    const int h0   = blockIdx.y * TH;
    const int w0   = blockIdx.x * TW;

    if (tid < 32) {
        const int wi = g * 64 + half_ * 32 + tid;
        wq_s[tid]  = wq[wi];
        wkv_s[tid] = make_float2(wk[wi], wv[wi]);
    } else if (tid >= 32 && tid < 60) {
        const float* ep = half_ ? w_emb : h_emb;
        emb_s[tid - 32] = ep[g * 28 + (tid - 32)];
    }
    __syncthreads();

    const float* xg = x + (size_t)(b * CIN + g * IG) * PLANE;
    const int cbase = half_ * OGH;

    // --- phase 1: grouped 1x1 conv k,v over haloed tile -> interleaved SMEM ---
    for (int p = tid; p < HH * HWD; p += NTHREADS) {
        const int yy = p / HWD;
        const int xx = p - yy * HWD;
        const int gy = h0 + yy - PAD;
        const int gx = w0 + xx - PAD;
        const bool inb = ((unsigned)gy < HNUM) & ((unsigned)gx < WNUM);
        const float* xb = xg + gy * WNUM + gx;
        float xi[IG];
        #pragma unroll
        for (int i = 0; i < IG; i++)
            xi[i] = inb ? __ldg(xb + i * PLANE) : 0.0f;
        #pragma unroll
        for (int c = 0; c < OGH; c++) {
            float kc = 0.0f, vc = 0.0f;
            #pragma unroll
            for (int i = 0; i < IG; i++) {
                const float2 w2 = wkv_s[c * IG + i];
                kc = fmaf(w2.x, xi[i], kc);
                vc = fmaf(w2.y, xi[i], vc);
            }
            *(float2*)&kv_s[c][yy][2 * xx] = make_float2(kc, vc);
        }
    }
    __syncthreads();

    // --- phase 2: attention; 2 adjacent px per thread, channels in pairs ---
    const int tc = tid & (TCN - 1);
    const int y_ = tid >> 4;
    const int x_ = 2 * tc;
    const int gh = h0 + y_;
    const int gw = w0 + x_;

    const float LOG2E = 1.4426950408889634f;

    float qsv[OGH][2];
    {
        float xi0[IG], xi1[IG];
        const float* xb = xg + gh * WNUM + gw;
        #pragma unroll
        for (int i = 0; i < IG; i++) {
            float2 t = __ldg((const float2*)(xb + i * PLANE));
            xi0[i] = t.x; xi1[i] = t.y;
        }
        #pragma unroll
        for (int c = 0; c < OGH; c++) {
            float q0 = 0.0f, q1 = 0.0f;
            #pragma unroll
            for (int i = 0; i < IG; i++) {
                q0 = fmaf(wq_s[c * IG + i], xi0[i], q0);
                q1 = fmaf(wq_s[c * IG + i], xi1[i], q1);
            }
            qsv[c][0] = q0 * LOG2E;
            qsv[c][1] = q1 * LOG2E;
        }
    }

    float* op = out + ((size_t)(b * CIN + g * OG + cbase) * HNUM + gh) * WNUM + gw;

    #pragma unroll 1
    for (int cp = 0; cp < OGH; cp += 2) {
        const int ca = cp, cb = cp + 1;
        float2 oA, oB;
        if (half_ == 0) {
            chan2<true>(&kv_s[ca][y_][2 * x_], &kv_s[cb][y_][2 * x_],
                        qsv[ca][0], qsv[ca][1], qsv[cb][0], qsv[cb][1],
                        &emb_s[ca * KW], &emb_s[cb * KW], oA, oB);
        } else {
            chan2<false>(&kv_s[ca][y_][2 * x_], &kv_s[cb][y_][2 * x_],
                         qsv[ca][0], qsv[ca][1], qsv[cb][0], qsv[cb][1],
                         &emb_s[ca * KW], &emb_s[cb * KW], oA, oB);
        }
        *(float2*)&op[(size_t)ca * PLANE] = oA;
        *(float2*)&op[(size_t)cb * PLANE] = oB;
    }
}

extern "C" void kernel_launch(void* const* d_in, const int* in_sizes, int n_in,
                              void* d_out, int out_size)
{
    const float* x     = (const float*)d_in[0];
    const float* wq    = (const float*)d_in[1];
    const float* wk    = (const float*)d_in[2];
    const float* wv    = (const float*)d_in[3];
    const float* h_emb = (const float*)d_in[4];
    const float* w_emb = (const float*)d_in[5];
    float* out = (float*)d_out;

    dim3 grid(WNUM / TW, HNUM / TH, BATCH * G * 2);  // (3, 8, 64) = 1536 blocks
    dim3 block(NTHREADS);
    attn_fused_kernel<<<grid, block>>>(x, wq, wk, wv, h_emb, w_emb, out);
}